// round 1
// baseline (speedup 1.0000x reference)
#include <cuda_runtime.h>
#include <math.h>

// ---------------------------------------------------------------------------
// MarkovBlanketAttention  (B=2, S=1024, DIN=512, DH=1024, H=16, HD=64)
//
// Outputs (flattened into d_out in tuple order):
//   s_out [B,S,DH], b_out [B,S,DH], z_out [B,S,DH],
//   sc_s  [B,H,S,S], sc_b [B,H,S,S], sc_z [B,H,S,S]
// ---------------------------------------------------------------------------

namespace {
constexpr int B_   = 2;
constexpr int S_   = 1024;
constexpr int DIN_ = 512;
constexpr int DH_  = 1024;
constexpr int H_   = 16;
constexpr int HD_  = 64;
constexpr int M_   = B_ * S_;                         // 2048 token rows
constexpr size_t NTOK = (size_t)M_ * DH_;             // 2,097,152
constexpr size_t NSC  = (size_t)B_ * H_ * S_ * S_;    // 33,554,432
}

// Scratch (device globals: no allocations allowed anywhere).
__device__ float g_q[3][NTOK];   // q_s, q_b, q_z
__device__ float g_k[3][NTOK];   // k_s, k_b, k_z
__device__ float g_v[3][NTOK];   // v_s, v_b, v_z
__device__ float g_o[3][NTOK];   // attention outputs ws, wb, wz
__device__ float g_p[3][NTOK];   // ws@Wo+co etc.
__device__ float g_w[3][NSC];    // softmax probabilities

// ---------------------------------------------------------------------------
// Generic SGEMM: C[M_,1024] (+)= A[M_,K] @ W[K,1024] + bias[1024]
// 128x128 block tile, BK=8, 256 threads, 8x8 per thread.
// Requires K % 8 == 0 (K = 512 or 1024 here).
// ---------------------------------------------------------------------------
template <bool ACC>
__global__ void __launch_bounds__(256) sgemm_kernel(
    const float* __restrict__ A, const float* __restrict__ W,
    const float* __restrict__ bias, float* __restrict__ C, int K) {
  constexpr int BM = 128, BN = 128, BK = 8;
  __shared__ float As[BK][BM];
  __shared__ float Bs[BK][BN];
  const int t  = threadIdx.x;
  const int bm = blockIdx.y * BM;
  const int bn = blockIdx.x * BN;

  const int arow = t >> 1;         // 0..127
  const int acol = (t & 1) * 4;    // 0 or 4
  const int brow = t >> 5;         // 0..7
  const int bcol = (t & 31) * 4;   // 0..124
  const int trow = (t >> 4) * 8;
  const int tcol = (t & 15) * 8;

  float acc[8][8];
#pragma unroll
  for (int i = 0; i < 8; i++)
#pragma unroll
    for (int j = 0; j < 8; j++) acc[i][j] = 0.f;

  for (int k0 = 0; k0 < K; k0 += BK) {
    float4 av = *(const float4*)(A + (size_t)(bm + arow) * K + k0 + acol);
    As[acol + 0][arow] = av.x;
    As[acol + 1][arow] = av.y;
    As[acol + 2][arow] = av.z;
    As[acol + 3][arow] = av.w;
    *(float4*)(&Bs[brow][bcol]) =
        *(const float4*)(W + (size_t)(k0 + brow) * DH_ + bn + bcol);
    __syncthreads();
#pragma unroll
    for (int kk = 0; kk < BK; kk++) {
      float a[8], b[8];
#pragma unroll
      for (int i = 0; i < 8; i++) a[i] = As[kk][trow + i];
#pragma unroll
      for (int j = 0; j < 8; j++) b[j] = Bs[kk][tcol + j];
#pragma unroll
      for (int i = 0; i < 8; i++)
#pragma unroll
        for (int j = 0; j < 8; j++) acc[i][j] = fmaf(a[i], b[j], acc[i][j]);
    }
    __syncthreads();
  }

#pragma unroll
  for (int i = 0; i < 8; i++) {
#pragma unroll
    for (int j = 0; j < 8; j++) {
      size_t idx = (size_t)(bm + trow + i) * DH_ + bn + tcol + j;
      float v = acc[i][j] + bias[bn + tcol + j];
      if (ACC) v += C[idx];
      C[idx] = v;
    }
  }
}

// ---------------------------------------------------------------------------
// Scores: out[b,h,q,k] = sum_d q[b,q,h*64+d] * k[b,k,h*64+d]   (raw, no bias)
// 64x64 output tile per block; grid (S/64, S/64, B*H).
// ---------------------------------------------------------------------------
__global__ void __launch_bounds__(256) scores_kernel(
    const float* __restrict__ q, const float* __restrict__ k,
    float* __restrict__ out) {
  const int bh = blockIdx.z;
  const int b  = bh >> 4;
  const int h  = bh & 15;
  const int q0 = blockIdx.y * 64;
  const int k0 = blockIdx.x * 64;
  __shared__ float Qs[64][65];
  __shared__ float Ks[64][65];
  const int t = threadIdx.x;

#pragma unroll
  for (int i = 0; i < 4; i++) {
    int f   = t + i * 256;       // float4 index 0..1023
    int row = f >> 4;            // 0..63
    int c   = (f & 15) * 4;      // 0..60
    float4 qv = *(const float4*)(q + (size_t)(b * S_ + q0 + row) * DH_ + h * HD_ + c);
    Qs[row][c + 0] = qv.x; Qs[row][c + 1] = qv.y;
    Qs[row][c + 2] = qv.z; Qs[row][c + 3] = qv.w;
    float4 kv = *(const float4*)(k + (size_t)(b * S_ + k0 + row) * DH_ + h * HD_ + c);
    Ks[row][c + 0] = kv.x; Ks[row][c + 1] = kv.y;
    Ks[row][c + 2] = kv.z; Ks[row][c + 3] = kv.w;
  }
  __syncthreads();

  const int trow = (t >> 4) * 4;
  const int tcol = (t & 15) * 4;
  float acc[4][4];
#pragma unroll
  for (int i = 0; i < 4; i++)
#pragma unroll
    for (int j = 0; j < 4; j++) acc[i][j] = 0.f;

#pragma unroll 16
  for (int d = 0; d < HD_; d++) {
    float a[4], bb[4];
#pragma unroll
    for (int i = 0; i < 4; i++) a[i] = Qs[trow + i][d];
#pragma unroll
    for (int j = 0; j < 4; j++) bb[j] = Ks[tcol + j][d];
#pragma unroll
    for (int i = 0; i < 4; i++)
#pragma unroll
      for (int j = 0; j < 4; j++) acc[i][j] = fmaf(a[i], bb[j], acc[i][j]);
  }

#pragma unroll
  for (int i = 0; i < 4; i++)
#pragma unroll
    for (int j = 0; j < 4; j++)
      out[((size_t)bh * S_ + q0 + trow + i) * S_ + k0 + tcol + j] = acc[i][j];
}

// ---------------------------------------------------------------------------
// Softmax over last dim of (scores + bias) -> probs. One block per row.
// ---------------------------------------------------------------------------
__global__ void __launch_bounds__(256) softmax_kernel(
    const float* __restrict__ sc, const float* __restrict__ bias,
    float* __restrict__ w) {
  const size_t row = blockIdx.x;
  const float* x  = sc + row * S_;
  const float* bi = bias + row * S_;
  float* wr = w + row * S_;
  const int t = threadIdx.x;

  float v[4];
  float m = -1e30f;
#pragma unroll
  for (int i = 0; i < 4; i++) {
    v[i] = x[t + i * 256] + bi[t + i * 256];
    m = fmaxf(m, v[i]);
  }
  __shared__ float red[256];
  red[t] = m;
  __syncthreads();
  for (int st = 128; st > 0; st >>= 1) {
    if (t < st) red[t] = fmaxf(red[t], red[t + st]);
    __syncthreads();
  }
  const float rowmax = red[0];
  __syncthreads();

  float sum = 0.f;
#pragma unroll
  for (int i = 0; i < 4; i++) {
    v[i] = expf(v[i] - rowmax);
    sum += v[i];
  }
  red[t] = sum;
  __syncthreads();
  for (int st = 128; st > 0; st >>= 1) {
    if (t < st) red[t] += red[t + st];
    __syncthreads();
  }
  const float inv = 1.f / red[0];
#pragma unroll
  for (int i = 0; i < 4; i++) wr[t + i * 256] = v[i] * inv;
}

// ---------------------------------------------------------------------------
// Attention output: o[b,q,h*64+c] = sum_k w[b,h,q,k] * v[b,k,h*64+c]
// 64 rows x 64 cols per block, BK=16; grid (S/64, B*H).
// ---------------------------------------------------------------------------
__global__ void __launch_bounds__(256) av_kernel(
    const float* __restrict__ w, const float* __restrict__ v,
    float* __restrict__ o) {
  const int bh = blockIdx.y;
  const int b  = bh >> 4;
  const int h  = bh & 15;
  const int r0 = blockIdx.x * 64;
  __shared__ float Ws[64][17];
  __shared__ float Vs[16][65];
  const int t = threadIdx.x;
  const int trow = (t >> 4) * 4;
  const int tcol = (t & 15) * 4;
  const int wrow = t >> 2;        // 0..63
  const int wc   = (t & 3) * 4;   // 0..12
  const int vrow = t >> 4;        // 0..15
  const int vc   = (t & 15) * 4;  // 0..60

  float acc[4][4];
#pragma unroll
  for (int i = 0; i < 4; i++)
#pragma unroll
    for (int j = 0; j < 4; j++) acc[i][j] = 0.f;

  for (int k0 = 0; k0 < S_; k0 += 16) {
    float4 wv = *(const float4*)(w + ((size_t)bh * S_ + r0 + wrow) * S_ + k0 + wc);
    Ws[wrow][wc + 0] = wv.x; Ws[wrow][wc + 1] = wv.y;
    Ws[wrow][wc + 2] = wv.z; Ws[wrow][wc + 3] = wv.w;
    float4 vv = *(const float4*)(v + (size_t)(b * S_ + k0 + vrow) * DH_ + h * HD_ + vc);
    Vs[vrow][vc + 0] = vv.x; Vs[vrow][vc + 1] = vv.y;
    Vs[vrow][vc + 2] = vv.z; Vs[vrow][vc + 3] = vv.w;
    __syncthreads();
#pragma unroll
    for (int kk = 0; kk < 16; kk++) {
      float a[4], bb[4];
#pragma unroll
      for (int i = 0; i < 4; i++) a[i] = Ws[trow + i][kk];
#pragma unroll
      for (int j = 0; j < 4; j++) bb[j] = Vs[kk][tcol + j];
#pragma unroll
      for (int i = 0; i < 4; i++)
#pragma unroll
        for (int j = 0; j < 4; j++) acc[i][j] = fmaf(a[i], bb[j], acc[i][j]);
    }
    __syncthreads();
  }

#pragma unroll
  for (int i = 0; i < 4; i++)
#pragma unroll
    for (int j = 0; j < 4; j++)
      o[(size_t)(b * S_ + r0 + trow + i) * DH_ + h * HD_ + tcol + j] = acc[i][j];
}

// ---------------------------------------------------------------------------
// Residual chain: s_out = s + p_s ; b_out = s_out + b + p_b ;
//                 z_out = b_out + z + p_z
// ---------------------------------------------------------------------------
__global__ void __launch_bounds__(256) combine_kernel(
    const float* __restrict__ s, const float* __restrict__ b,
    const float* __restrict__ z, const float* __restrict__ ps,
    const float* __restrict__ pb, const float* __restrict__ pz,
    float* __restrict__ os, float* __restrict__ ob, float* __restrict__ oz) {
  size_t i = (size_t)blockIdx.x * 256 + threadIdx.x;
  if (i >= NTOK) return;
  float so = s[i] + ps[i];
  float bo = so + b[i] + pb[i];
  float zo = bo + z[i] + pz[i];
  os[i] = so;
  ob[i] = bo;
  oz[i] = zo;
}

// ---------------------------------------------------------------------------
extern "C" void kernel_launch(void* const* d_in, const int* in_sizes, int n_in,
                              void* d_out, int out_size) {
  const float* y    = (const float*)d_in[0];
  const float* s    = (const float*)d_in[1];
  const float* b    = (const float*)d_in[2];
  const float* z    = (const float*)d_in[3];
  const float* bias_att[3] = {(const float*)d_in[4], (const float*)d_in[5],
                              (const float*)d_in[6]};
  const float* Wqs  = (const float*)d_in[7];
  const float* cqs  = (const float*)d_in[8];
  const float* Wqb  = (const float*)d_in[9];
  const float* cqb  = (const float*)d_in[10];
  const float* Wqz  = (const float*)d_in[11];
  const float* cqz  = (const float*)d_in[12];
  const float* Wkss = (const float*)d_in[13];
  const float* ckss = (const float*)d_in[14];
  const float* Wksb = (const float*)d_in[15];
  const float* cksb = (const float*)d_in[16];
  const float* Wkzb = (const float*)d_in[17];
  const float* ckzb = (const float*)d_in[18];
  const float* Wkbb = (const float*)d_in[19];
  const float* ckbb = (const float*)d_in[20];
  const float* Wkzz = (const float*)d_in[21];
  const float* ckzz = (const float*)d_in[22];
  const float* Wvs  = (const float*)d_in[23];
  const float* cvs  = (const float*)d_in[24];
  const float* Wvb  = (const float*)d_in[25];
  const float* cvb  = (const float*)d_in[26];
  const float* Wvz  = (const float*)d_in[27];
  const float* cvz  = (const float*)d_in[28];
  const float* Wo   = (const float*)d_in[29];
  const float* co   = (const float*)d_in[30];

  float* out   = (float*)d_out;
  float* s_out = out;
  float* b_out = out + NTOK;
  float* z_out = out + 2 * NTOK;
  float* sc[3] = {out + 3 * NTOK, out + 3 * NTOK + NSC, out + 3 * NTOK + 2 * NSC};

  float *gq, *gk, *gv, *go, *gp, *gw;
  cudaGetSymbolAddress((void**)&gq, g_q);
  cudaGetSymbolAddress((void**)&gk, g_k);
  cudaGetSymbolAddress((void**)&gv, g_v);
  cudaGetSymbolAddress((void**)&go, g_o);
  cudaGetSymbolAddress((void**)&gp, g_p);
  cudaGetSymbolAddress((void**)&gw, g_w);

  const dim3 ggrid(DH_ / 128, M_ / 128);  // (8, 16)

  // Q projections (K = DIN = 512)
  sgemm_kernel<false><<<ggrid, 256>>>(y, Wqs, cqs, gq + 0 * NTOK, DIN_);
  sgemm_kernel<false><<<ggrid, 256>>>(y, Wqb, cqb, gq + 1 * NTOK, DIN_);
  sgemm_kernel<false><<<ggrid, 256>>>(y, Wqz, cqz, gq + 2 * NTOK, DIN_);

  // K projections (K = DH = 1024), with accumulation per the reference algebra
  sgemm_kernel<false><<<ggrid, 256>>>(s, Wkss, ckss, gk + 0 * NTOK, DH_);
  sgemm_kernel<true ><<<ggrid, 256>>>(b, Wksb, cksb, gk + 0 * NTOK, DH_);

  sgemm_kernel<false><<<ggrid, 256>>>(b, Wkbb, ckbb, gk + 1 * NTOK, DH_);
  sgemm_kernel<true ><<<ggrid, 256>>>(s, Wksb, cksb, gk + 1 * NTOK, DH_);
  sgemm_kernel<true ><<<ggrid, 256>>>(z, Wkzb, ckzb, gk + 1 * NTOK, DH_);

  sgemm_kernel<false><<<ggrid, 256>>>(z, Wkzz, ckzz, gk + 2 * NTOK, DH_);
  sgemm_kernel<true ><<<ggrid, 256>>>(b, Wkzb, ckzb, gk + 2 * NTOK, DH_);

  // V projections
  sgemm_kernel<false><<<ggrid, 256>>>(s, Wvs, cvs, gv + 0 * NTOK, DH_);
  sgemm_kernel<false><<<ggrid, 256>>>(b, Wvb, cvb, gv + 1 * NTOK, DH_);
  sgemm_kernel<false><<<ggrid, 256>>>(z, Wvz, cvz, gv + 2 * NTOK, DH_);

  // Attention per stream type
  const dim3 sgrid(S_ / 64, S_ / 64, B_ * H_);  // (16,16,32)
  const dim3 agrid(S_ / 64, B_ * H_);           // (16,32)
  for (int t = 0; t < 3; t++) {
    scores_kernel<<<sgrid, 256>>>(gq + t * NTOK, gk + t * NTOK, sc[t]);
    softmax_kernel<<<B_ * H_ * S_, 256>>>(sc[t], bias_att[t], gw + t * NSC);
    av_kernel<<<agrid, 256>>>(gw + t * NSC, gv + t * NTOK, go + t * NTOK);
    sgemm_kernel<false><<<ggrid, 256>>>(go + t * NTOK, Wo, co, gp + t * NTOK, DH_);
  }

  // Residual chain
  combine_kernel<<<(int)((NTOK + 255) / 256), 256>>>(
      s, b, z, gp + 0 * NTOK, gp + 1 * NTOK, gp + 2 * NTOK,
      s_out, b_out, z_out);
}